// round 12
// baseline (speedup 1.0000x reference)
#include <cuda_runtime.h>
#include <cstdint>

#define B 64
#define K 8
#define V 128000
#define NCH 8
#define CH 16000          // V / NCH
#define PLACEHOLDER_F (-1.0f)

// scratch (no allocations allowed)
__device__ int   g_na[B];
__device__ float g_csum[B * NCH];

__device__ __forceinline__ void st_cg_i32(int* p, int v) {
    asm volatile("st.global.cg.s32 [%0], %1;" :: "l"(p), "r"(v) : "memory");
}
__device__ __forceinline__ void st_cg_f32(float* p, float v) {
    asm volatile("st.global.cg.f32 [%0], %1;" :: "l"(p), "f"(v) : "memory");
}
__device__ __forceinline__ int ld_cg_i32(const int* p) {
    int v; asm volatile("ld.global.cg.s32 %0, [%1];" : "=r"(v) : "l"(p) : "memory"); return v;
}
__device__ __forceinline__ float ld_cg_f32(const float* p) {
    float v; asm volatile("ld.global.cg.f32 %0, [%1];" : "=f"(v) : "l"(p) : "memory"); return v;
}

// ---------------------------------------------------------------------------
// One kernel, one cluster (8 CTAs) per batch.
//   rank 0: accept gathers + na + static outputs
//   cluster barrier (release/acquire, cluster scope -> no chip-wide fences)
//   all ranks: stream chunk residual sum
//   cluster barrier
//   rank 0: cumsum, threshold search, crossing-chunk re-read (L2-hot), token
// ---------------------------------------------------------------------------
__global__ void __launch_bounds__(256) __cluster_dims__(NCH, 1, 1)
k_all(const int* __restrict__ dtok,
      const float* __restrict__ dp,
      const float* __restrict__ tp,
      const int* __restrict__ bonus,
      const float* __restrict__ us,
      float* __restrict__ out) {
    int r = blockIdx.x;          // rank in cluster = chunk 0..7
    int b = blockIdx.y;          // batch
    int t = threadIdx.x;         // 256

    // ---- phase 1: rank 0 computes accept bits / na, writes static outputs ----
    if (r == 0) {
        __shared__ int s_acc[K];
        if (t < K) {
            int tok = dtok[b * K + t];
            size_t off = (size_t)(b * K + t) * V + (size_t)tok;
            float p = __ldg(tp + off);
            float q = __ldg(dp + off);
            float u = us[b * K + t];
            float ap = fminf(1.0f, p / fmaxf(q, 1e-10f));
            s_acc[t] = (u < ap) ? 1 : 0;
        }
        __syncthreads();
        if (t == 0) {
            int na = 0;
            for (int i = 0; i < K; i++) { if (s_acc[i]) na++; else break; }
            st_cg_i32(&g_na[b], na);
            bool all = (na == K);
            for (int pos = 0; pos <= K; pos++) {
                if (pos < na) {
                    out[b * (K + 1) + pos] = (float)dtok[b * K + pos];
                } else if (pos == na) {
                    if (all) out[b * (K + 1) + pos] = (float)bonus[b];
                    // else: phase-3 finalize writes the recovered token here
                } else {
                    out[b * (K + 1) + pos] = PLACEHOLDER_F;
                }
            }
            int ob = B * (K + 1);
            out[ob + b]         = (float)na;          // num_accepted
            out[ob + B + b]     = (float)na;          // accepted_counts
            out[ob + 2 * B + b] = all ? 0.0f : 1.0f;  // recovered_counts
            out[ob + 3 * B + b] = all ? 1.0f : 0.0f;  // bonus_counts
        }
    }

    // cluster barrier #1: na visible (arrive=release, wait=acquire, cluster scope)
    asm volatile("barrier.cluster.arrive.aligned;" ::: "memory");
    asm volatile("barrier.cluster.wait.aligned;"   ::: "memory");

    int na = ld_cg_i32(&g_na[b]);
    int j  = (na < K) ? na : (K - 1);
    size_t row = ((size_t)(b * K + j)) * V;

    // ---- phase 2: stream this rank's chunk ----
    {
        size_t base = row + (size_t)r * CH;
        const float4* t4 = (const float4*)(tp + base);
        const float4* d4 = (const float4*)(dp + base);
        float s = 0.0f;
        const int N4 = CH / 4;   // 4000 -> ~16 iters/thread
        #pragma unroll 4
        for (int i = t; i < N4; i += 256) {
            float4 tv = t4[i];
            float4 dv = d4[i];
            s += fmaxf(tv.x - dv.x, 0.0f);
            s += fmaxf(tv.y - dv.y, 0.0f);
            s += fmaxf(tv.z - dv.z, 0.0f);
            s += fmaxf(tv.w - dv.w, 0.0f);
        }
        for (int o = 16; o > 0; o >>= 1) s += __shfl_down_sync(0xffffffffu, s, o);
        __shared__ float wsum[8];
        if ((t & 31) == 0) wsum[t >> 5] = s;
        __syncthreads();
        if (t == 0) {
            float tot = 0.0f;
            #pragma unroll
            for (int w = 0; w < 8; w++) tot += wsum[w];
            st_cg_f32(&g_csum[b * NCH + r], tot);
        }
    }

    // cluster barrier #2: all chunk sums visible
    asm volatile("barrier.cluster.arrive.aligned;" ::: "memory");
    asm volatile("barrier.cluster.wait.aligned;"   ::: "memory");

    if (r != 0) return;

    // ---- phase 3: finalize (rank 0 only) ----
    __shared__ float thr_s, pref_s, total_s;
    __shared__ int   cidx, cand;
    __shared__ float segsum[256];
    __shared__ float segex[256];

    if (t == 0) {
        float cum[NCH];
        float run = 0.0f;
        #pragma unroll
        for (int ci = 0; ci < NCH; ci++) {
            run += ld_cg_f32(&g_csum[b * NCH + ci]);
            cum[ci] = run;
        }
        total_s = run;
        float thr = us[b * K + j] * run;
        thr_s = thr;
        int cc = NCH - 1;
        #pragma unroll
        for (int i = 0; i < NCH; i++) if (cum[i] > thr) { cc = i; break; }
        cidx = cc;
        pref_s = (cc > 0) ? cum[cc - 1] : 0.0f;
        cand = V - 1;   // safety default (measure-zero boundary rounding)
    }
    __syncthreads();

    int rec;
    if (total_s > 0.0f) {
        int cc = cidx;
        size_t fbase = row + (size_t)cc * CH;

        // pass 1: per-thread contiguous segment sums (63 elems, L2-hot re-read)
        const int SEG = (CH + 255) / 256;   // 63
        int s0 = t * SEG;
        float ls = 0.0f;
        for (int e = 0; e < SEG; e++) {
            int ii = s0 + e;
            if (ii < CH) ls += fmaxf(tp[fbase + ii] - dp[fbase + ii], 0.0f);
        }
        segsum[t] = ls;
        __syncthreads();
        if (t == 0) {
            float run = pref_s;
            for (int i = 0; i < 256; i++) { segex[i] = run; run += segsum[i]; }
        }
        __syncthreads();

        // pass 2: locate crossing within this thread's segment
        {
            float run = segex[t];
            float thr = thr_s;
            for (int e = 0; e < SEG; e++) {
                int ii = s0 + e;
                if (ii >= CH) break;
                run += fmaxf(tp[fbase + ii] - dp[fbase + ii], 0.0f);
                if (run > thr) { atomicMin(&cand, cc * CH + ii); break; }
            }
        }
        __syncthreads();
        rec = cand;
    } else {
        // lazy fallback: full-row argmax of target (first occurrence) — never
        // taken on softmax inputs, kept for strict correctness
        __shared__ float amx[256];
        __shared__ int   ami[256];
        float mx = -1.0f; int mi = V;
        for (int i = t; i < V; i += 256) {
            float v = tp[row + i];
            if (v > mx) { mx = v; mi = i; }
        }
        amx[t] = mx; ami[t] = mi;
        __syncthreads();
        for (int st = 128; st > 0; st >>= 1) {
            if (t < st) {
                float ov = amx[t + st]; int oi = ami[t + st];
                if (ov > amx[t] || (ov == amx[t] && oi < ami[t])) {
                    amx[t] = ov; ami[t] = oi;
                }
            }
            __syncthreads();
        }
        rec = ami[0];
    }

    if (t == 0 && na < K) out[b * (K + 1) + na] = (float)rec;
}

// ---------------------------------------------------------------------------
extern "C" void kernel_launch(void* const* d_in, const int* in_sizes, int n_in,
                              void* d_out, int out_size) {
    const int*   dtok  = (const int*)d_in[0];   // [B,K]
    const float* dp    = (const float*)d_in[1]; // [B,K,V] draft probs
    const float* tp    = (const float*)d_in[2]; // [B,K,V] target probs
    const int*   bonus = (const int*)d_in[3];   // [B]
    const float* us    = (const float*)d_in[4]; // [B,K]
    float* out = (float*)d_out;

    dim3 g(NCH, B);
    k_all<<<g, 256>>>(dtok, dp, tp, bonus, us, out);
}

// round 17
// speedup vs baseline: 2.9592x; 2.9592x over previous
#include <cuda_runtime.h>
#include <cstdint>

#define B 64
#define K 8
#define V 128000
#define NCH 32
#define CH 4000           // V / NCH
#define PLACEHOLDER_F (-1.0f)

// scratch (no allocations allowed)
__device__ float g_csum[B * NCH];

__device__ __forceinline__ void st_cg_f32(float* p, float v) {
    asm volatile("st.global.cg.f32 [%0], %1;" :: "l"(p), "f"(v) : "memory");
}
__device__ __forceinline__ float ld_cg_f32(const float* p) {
    float v; asm volatile("ld.global.cg.f32 %0, [%1];" : "=f"(v) : "l"(p) : "memory"); return v;
}

// ---------------------------------------------------------------------------
// k2g: grid (NCH, B), 256 thr. Every block derives na itself via a 16-load
//      gather prologue (addresses identical within a batch -> L2-hot after the
//      first touch). NO fences, NO elections, NO spins. Then streams chunk c.
//      c==0 block also writes the static output fields.
// ---------------------------------------------------------------------------
__global__ void __launch_bounds__(256) k2g(const int* __restrict__ dtok,
                                           const float* __restrict__ dp,
                                           const float* __restrict__ tp,
                                           const int* __restrict__ bonus,
                                           const float* __restrict__ us,
                                           float* __restrict__ out) {
    int c = blockIdx.x;          // chunk 0..NCH-1
    int b = blockIdx.y;          // batch 0..63
    int t = threadIdx.x;         // 256

    // ---- prologue: 16 concurrent gathers -> accept prefix length na ----
    __shared__ float s_p[K], s_q[K];
    __shared__ int s_na;
    if (t < 2 * K) {
        int k = t & (K - 1);
        int tok = __ldg(dtok + b * K + k);
        size_t off = (size_t)(b * K + k) * V + (size_t)tok;
        if (t < K) s_p[k] = __ldg(tp + off);
        else       s_q[k] = __ldg(dp + off);
    }
    __syncthreads();
    if (t == 0) {
        int n = 0;
        for (int i = 0; i < K; i++) {
            float ap = fminf(1.0f, s_p[i] / fmaxf(s_q[i], 1e-10f));
            if (__ldg(us + b * K + i) < ap) n++; else break;
        }
        s_na = n;
    }
    __syncthreads();
    int na = s_na;
    int j  = (na < K) ? na : (K - 1);

    // ---- stream chunk c of row j ----
    size_t base = ((size_t)(b * K + j)) * V + (size_t)c * CH;
    const float4* t4 = (const float4*)(tp + base);
    const float4* d4 = (const float4*)(dp + base);

    float s = 0.0f;
    const int N4 = CH / 4;       // 1000
    #pragma unroll 4
    for (int i = t; i < N4; i += 256) {
        float4 tv = t4[i];
        float4 dv = d4[i];
        s += fmaxf(tv.x - dv.x, 0.0f);
        s += fmaxf(tv.y - dv.y, 0.0f);
        s += fmaxf(tv.z - dv.z, 0.0f);
        s += fmaxf(tv.w - dv.w, 0.0f);
    }

    for (int o = 16; o > 0; o >>= 1) s += __shfl_down_sync(0xffffffffu, s, o);
    __shared__ float wsum[8];
    if ((t & 31) == 0) wsum[t >> 5] = s;
    __syncthreads();
    if (t == 0) {
        float tot = 0.0f;
        #pragma unroll
        for (int w = 0; w < 8; w++) tot += wsum[w];
        st_cg_f32(&g_csum[b * NCH + c], tot);
    }

    // ---- static output fields (chunk-0 block only) ----
    if (c == 0 && t == 0) {
        bool all = (na == K);
        for (int pos = 0; pos <= K; pos++) {
            if (pos < na) {
                out[b * (K + 1) + pos] = (float)dtok[b * K + pos];
            } else if (pos == na) {
                if (all) out[b * (K + 1) + pos] = (float)bonus[b];
                // else: k3 writes the recovered token here
            } else {
                out[b * (K + 1) + pos] = PLACEHOLDER_F;
            }
        }
        int ob = B * (K + 1);
        out[ob + b]         = (float)na;          // num_accepted
        out[ob + B + b]     = (float)na;          // accepted_counts
        out[ob + 2 * B + b] = all ? 0.0f : 1.0f;  // recovered_counts
        out[ob + 3 * B + b] = all ? 1.0f : 0.0f;  // bonus_counts
    }
}

// ---------------------------------------------------------------------------
// Kernel 3: one block per batch; recompute na (gathers L2-hot), chunk cumsum,
//           threshold search, L2-hot re-read of crossing chunk, token write.
// ---------------------------------------------------------------------------
__global__ void __launch_bounds__(256) k3_finalize(const int* __restrict__ dtok,
                                                   const float* __restrict__ dp,
                                                   const float* __restrict__ tp,
                                                   const float* __restrict__ us,
                                                   float* __restrict__ out) {
    int b = blockIdx.x;
    int t = threadIdx.x;   // 256

    __shared__ float s_p[K], s_q[K];
    __shared__ float thr_s, pref_s, total_s;
    __shared__ int   s_na, cidx, cand;
    __shared__ float segsum[256];
    __shared__ float segex[256];

    if (t < 2 * K) {
        int k = t & (K - 1);
        int tok = __ldg(dtok + b * K + k);
        size_t off = (size_t)(b * K + k) * V + (size_t)tok;
        if (t < K) s_p[k] = __ldg(tp + off);
        else       s_q[k] = __ldg(dp + off);
    }
    __syncthreads();
    if (t == 0) {
        int n = 0;
        for (int i = 0; i < K; i++) {
            float ap = fminf(1.0f, s_p[i] / fmaxf(s_q[i], 1e-10f));
            if (__ldg(us + b * K + i) < ap) n++; else break;
        }
        s_na = n;
    }
    __syncthreads();
    int na = s_na;
    int j  = (na < K) ? na : (K - 1);
    size_t row = ((size_t)(b * K + j)) * V;

    if (t == 0) {
        float cum[NCH];
        float run = 0.0f;
        for (int ci = 0; ci < NCH; ci++) {
            run += ld_cg_f32(&g_csum[b * NCH + ci]);
            cum[ci] = run;
        }
        total_s = run;
        float thr = us[b * K + j] * run;
        thr_s = thr;
        int cc = NCH - 1;
        for (int i = 0; i < NCH; i++) if (cum[i] > thr) { cc = i; break; }
        cidx = cc;
        pref_s = (cc > 0) ? cum[cc - 1] : 0.0f;
        cand = V - 1;   // safety default (measure-zero boundary rounding)
    }
    __syncthreads();

    int rec;
    if (total_s > 0.0f) {
        int cc = cidx;
        size_t fbase = row + (size_t)cc * CH;

        // pass 1: per-thread contiguous segment sums (16 elems; L2-hot re-read)
        const int SEG = (CH + 255) / 256;   // 16
        int s0 = t * SEG;
        float ls = 0.0f;
        #pragma unroll
        for (int e = 0; e < SEG; e++) {
            int ii = s0 + e;
            if (ii < CH) ls += fmaxf(tp[fbase + ii] - dp[fbase + ii], 0.0f);
        }
        segsum[t] = ls;
        __syncthreads();
        if (t == 0) {
            float run = pref_s;
            for (int i = 0; i < 256; i++) { segex[i] = run; run += segsum[i]; }
        }
        __syncthreads();

        // pass 2: locate crossing within this thread's segment (L1/L2-hot)
        {
            float run = segex[t];
            float thr = thr_s;
            #pragma unroll
            for (int e = 0; e < SEG; e++) {
                int ii = s0 + e;
                if (ii >= CH) break;
                run += fmaxf(tp[fbase + ii] - dp[fbase + ii], 0.0f);
                if (run > thr) { atomicMin(&cand, cc * CH + ii); break; }
            }
        }
        __syncthreads();
        rec = cand;
    } else {
        // lazy fallback: full-row argmax of target (first occurrence) — never
        // taken on softmax inputs, kept for strict correctness
        __shared__ float amx[256];
        __shared__ int   ami[256];
        float mx = -1.0f; int mi = V;
        for (int i = t; i < V; i += 256) {
            float v = tp[row + i];
            if (v > mx) { mx = v; mi = i; }
        }
        amx[t] = mx; ami[t] = mi;
        __syncthreads();
        for (int st = 128; st > 0; st >>= 1) {
            if (t < st) {
                float ov = amx[t + st]; int oi = ami[t + st];
                if (ov > amx[t] || (ov == amx[t] && oi < ami[t])) {
                    amx[t] = ov; ami[t] = oi;
                }
            }
            __syncthreads();
        }
        rec = ami[0];
    }

    if (t == 0 && na < K) out[b * (K + 1) + na] = (float)rec;
}

// ---------------------------------------------------------------------------
extern "C" void kernel_launch(void* const* d_in, const int* in_sizes, int n_in,
                              void* d_out, int out_size) {
    const int*   dtok  = (const int*)d_in[0];   // [B,K]
    const float* dp    = (const float*)d_in[1]; // [B,K,V] draft probs
    const float* tp    = (const float*)d_in[2]; // [B,K,V] target probs
    const int*   bonus = (const int*)d_in[3];   // [B]
    const float* us    = (const float*)d_in[4]; // [B,K]
    float* out = (float*)d_out;

    dim3 g2(NCH, B);
    k2g<<<g2, 256>>>(dtok, dp, tp, bonus, us, out);
    k3_finalize<<<B, 256>>>(dtok, dp, tp, us, out);
}